// round 8
// baseline (speedup 1.0000x reference)
#include <cuda_runtime.h>

typedef unsigned long long u64;

__device__ __forceinline__ u64 pk2(float lo, float hi){
  u64 r; asm("mov.b64 %0, {%1, %2};" : "=l"(r) : "f"(lo), "f"(hi)); return r;
}
__device__ __forceinline__ u64 ffma2(u64 a, u64 b, u64 c){
  u64 r; asm("fma.rn.f32x2 %0, %1, %2, %3;" : "=l"(r) : "l"(a), "l"(b), "l"(c)); return r;
}
__device__ __forceinline__ u64 fmul2(u64 a, u64 b){
  u64 r; asm("mul.rn.f32x2 %0, %1, %2;" : "=l"(r) : "l"(a), "l"(b)); return r;
}
__device__ __forceinline__ u64 fadd2(u64 a, u64 b){
  u64 r; asm("add.rn.f32x2 %0, %1, %2;" : "=l"(r) : "l"(a), "l"(b)); return r;
}
// Register-pair alias views (no asm movs; ptxas folds).
__device__ __forceinline__ float lo2(u64 v){ return reinterpret_cast<float2*>(&v)->x; }
__device__ __forceinline__ float hi2(u64 v){ return reinterpret_cast<float2*>(&v)->y; }

#define NWARP 8
#define GRID_BLOCKS 608   // 152 SMs * 4 resident blocks

// Fused PillarVFE, persistent warps, one pillar per warp-iteration.
//   pre[n,o] = A[o]x + B[o]y + C[o]z + D[o]w + bias_p[o]
//   out[o]   = max( max_{n<npts} pre, npts<32 ? bn_bias[o] : -inf, 0 )
// Max over UNBIASED dots; per-pillar bias added once (max-monotone).
// Lanes >= npts stage point 0 (max-idempotent), so the quad math is
// BRANCH-FREE: points 0-15 always, points 16-31 under one uniform test.
__global__ __launch_bounds__(256, 4) void pillar_vfe_kernel(
    const float4* __restrict__ voxels,   // [P,32] xyzw
    const float*  __restrict__ W,        // [64,9]
    const float*  __restrict__ gamma,
    const float*  __restrict__ beta,
    const float*  __restrict__ rmean,
    const float*  __restrict__ rvar,
    const int*    __restrict__ vnum,     // [P]
    const int*    __restrict__ vcoords,  // [P,4] (b,z,y,x)
    float*        __restrict__ out,      // [P,64]
    int P)
{
  __shared__ float cf[10][64];                         // folded coefficients
  __shared__ __align__(16) float shp[NWARP][2][4][32]; // double-buffered staging

  int tid = threadIdx.x;
  if (tid < 64) {
    int o = tid;
    float s = gamma[o] / sqrtf(rvar[o] + 1e-3f);
    const float* w = W + o * 9;
    float w0=w[0], w1=w[1], w2=w[2], w3=w[3], w4=w[4], w5=w[5], w6=w[6], w7=w[7], w8=w[8];
    float S0 = w0 + w7, S1 = w1 + w8;   // xc / yc channels duplicated (c0+c7, c1+c8)
    cf[0][o] = s * (S0 + w4);           // * x
    cf[1][o] = s * (S1 + w5);           // * y
    cf[2][o] = s * (w2 + w6);           // * z
    cf[3][o] = s * w3;                  // * intensity
    cf[4][o] = s * S0;                  // * cx
    cf[5][o] = s * S1;                  // * cy
    cf[6][o] = s * w4;                  // * mx
    cf[7][o] = s * w5;                  // * my
    cf[8][o] = s * w6;                  // * mz
    cf[9][o] = beta[o] - rmean[o] * s;  // BN bias (= masked-point pre-activation)
  }
  __syncthreads();

  int lane = tid & 31;
  int wrp  = tid >> 5;
  int NWt  = gridDim.x * NWARP;
  int p    = blockIdx.x * NWARP + wrp;
  if (p >= P) return;

  // ---- Hoisted per-warp constants. Lane owns channels c0=2*lane, c1=2*lane+1.
  int c0 = 2 * lane, c1 = 2 * lane + 1;
  u64 pA0 = pk2(cf[0][c0], cf[0][c0]), pA1 = pk2(cf[0][c1], cf[0][c1]);
  u64 pB0 = pk2(cf[1][c0], cf[1][c0]), pB1 = pk2(cf[1][c1], cf[1][c1]);
  u64 pC0 = pk2(cf[2][c0], cf[2][c0]), pC1 = pk2(cf[2][c1], cf[2][c1]);
  u64 pD0 = pk2(cf[3][c0], cf[3][c0]), pD1 = pk2(cf[3][c1], cf[3][c1]);
  float n4a = -cf[4][c0], n4b = -cf[4][c1];
  float n5a = -cf[5][c0], n5b = -cf[5][c1];
  float n6a = -cf[6][c0], n6b = -cf[6][c1];
  float n7a = -cf[7][c0], n7b = -cf[7][c1];
  float n8a = -cf[8][c0], n8b = -cf[8][c1];
  float bb0 = cf[9][c0], bb1 = cf[9][c1];
  float rbb0 = fmaxf(bb0, 0.0f), rbb1 = fmaxf(bb1, 0.0f);

  float* sbase = &shp[wrp][0][0][0];
  int bufoff = 0;                        // toggles 0 / 128 floats

  // ---- Current pillar state.
  float4 v  = voxels[(size_t)p * 32 + lane];                               // LDG.128
  int np    = vnum[p];
  int2 cyx  = *reinterpret_cast<const int2*>(vcoords + (size_t)p * 4 + 2); // (y,x)

  for (;;) {
    // Prefetch next pillar (hides DRAM latency behind this pillar's compute).
    int pn = p + NWt;
    bool more = (pn < P);
    float4 vN; int npN = 0; int2 cyxN = make_int2(0, 0);
    if (more) {
      vN   = voxels[(size_t)pn * 32 + lane];
      npN  = vnum[pn];
      cyxN = *reinterpret_cast<const int2*>(vcoords + (size_t)pn * 4 + 2);
    }

    // Mean sums over ALL 32 points (reference sums unmasked).
    // 64-bit shuffle butterfly on packed (x,y) + scalar z.
    u64  sxy = pk2(v.x, v.y);
    float sz = v.z;
    #pragma unroll
    for (int off = 16; off; off >>= 1) {
      u64 o2 = __shfl_xor_sync(0xffffffffu, sxy, off);
      float oz = __shfl_xor_sync(0xffffffffu, sz, off);
      sxy = fadd2(sxy, o2);
      sz += oz;
    }

    // Stage transposed points; pad invalid lanes with point 0 (max-idempotent).
    float x0 = __shfl_sync(0xffffffffu, v.x, 0);
    float y0 = __shfl_sync(0xffffffffu, v.y, 0);
    float z0 = __shfl_sync(0xffffffffu, v.z, 0);
    float w0 = __shfl_sync(0xffffffffu, v.w, 0);
    bool valid = (lane < np);
    float* sb = sbase + bufoff;
    sb[lane]      = valid ? v.x : x0;
    sb[32 + lane] = valid ? v.y : y0;
    sb[64 + lane] = valid ? v.z : z0;
    sb[96 + lane] = valid ? v.w : w0;
    __syncwarp();

    const ulonglong2* rq = reinterpret_cast<const ulonglong2*>(sb);
    float m0 = -3.4e38f, m1 = -3.4e38f;

    // One quad = 4 points: 4x LDS.128 broadcast + 16 FFMA2 + 8 FMNMX, no branches.
#define QUAD(qq)                                                              \
    {                                                                         \
      ulonglong2 X = rq[qq],      Y  = rq[8 + qq];                            \
      ulonglong2 Z = rq[16 + qq], Wv = rq[24 + qq];                           \
      u64 s01 = fmul2(pA0, X.x);  s01 = ffma2(pB0, Y.x, s01);                 \
      u64 s23 = fmul2(pA0, X.y);  s23 = ffma2(pB0, Y.y, s23);                 \
      u64 r01 = fmul2(pA1, X.x);  r01 = ffma2(pB1, Y.x, r01);                 \
      u64 r23 = fmul2(pA1, X.y);  r23 = ffma2(pB1, Y.y, r23);                 \
      s01 = ffma2(pC0, Z.x, s01); s01 = ffma2(pD0, Wv.x, s01);                \
      s23 = ffma2(pC0, Z.y, s23); s23 = ffma2(pD0, Wv.y, s23);                \
      r01 = ffma2(pC1, Z.x, r01); r01 = ffma2(pD1, Wv.x, r01);                \
      r23 = ffma2(pC1, Z.y, r23); r23 = ffma2(pD1, Wv.y, r23);                \
      m0 = fmaxf(m0, fmaxf(fmaxf(lo2(s01), hi2(s01)),                        \
                           fmaxf(lo2(s23), hi2(s23))));                      \
      m1 = fmaxf(m1, fmaxf(fmaxf(lo2(r01), hi2(r01)),                        \
                           fmaxf(lo2(r23), hi2(r23))));                      \
    }

    // Points 0-15: always (straight-line, 4 independent quads).
    QUAD(0) QUAD(1) QUAD(2) QUAD(3)
    // Points 16-31: one warp-uniform branch (~50% taken).
    if (np > 16) {
      QUAD(4) QUAD(5) QUAD(6) QUAD(7)
    }
#undef QUAD

    // Scalar per-pillar bias chains (5 FFMA each).
    float rn = __fdividef(1.0f, (float)np);
    float mx = lo2(sxy) * rn, my = hi2(sxy) * rn, mz = sz * rn;
    float cx = fmaf((float)cyx.y, 0.16f, 0.08f);
    float cy = fmaf((float)cyx.x, 0.16f, -39.6f);
    float bias0 = fmaf(mz, n8a, fmaf(my, n7a, fmaf(mx, n6a,
                  fmaf(cy, n5a, fmaf(cx, n4a, bb0)))));
    float bias1 = fmaf(mz, n8b, fmaf(my, n7b, fmaf(mx, n6b,
                  fmaf(cy, n5b, fmaf(cx, n4b, bb1)))));

    // Epilogue: bias, relu floor (incl. masked-point bn contribution), store.
    float g0 = (np < 32) ? rbb0 : 0.0f;
    float g1 = (np < 32) ? rbb1 : 0.0f;
    float2 res = make_float2(fmaxf(m0 + bias0, g0), fmaxf(m1 + bias1, g1));
    reinterpret_cast<float2*>(out)[(size_t)p * 32 + lane] = res;  // ch (2l,2l+1)

    if (!more) break;
    v = vN; np = npN; cyx = cyxN; p = pn;
    bufoff ^= 128;
  }
}

extern "C" void kernel_launch(void* const* d_in, const int* in_sizes, int n_in,
                              void* d_out, int out_size) {
  const float4* voxels = (const float4*)d_in[0];
  const float*  W      = (const float*)d_in[1];
  const float*  gamma  = (const float*)d_in[2];
  const float*  beta   = (const float*)d_in[3];
  const float*  rmean  = (const float*)d_in[4];
  const float*  rvar   = (const float*)d_in[5];
  const int*    vnum   = (const int*)d_in[6];
  const int*    vcrd   = (const int*)d_in[7];
  float* out = (float*)d_out;

  int P = in_sizes[6];
  int needed = (P + NWARP - 1) / NWARP;
  int blocks = needed < GRID_BLOCKS ? needed : GRID_BLOCKS;
  pillar_vfe_kernel<<<blocks, 256>>>(voxels, W, gamma, beta, rmean, rvar,
                                     vnum, vcrd, out, P);
}

// round 9
// speedup vs baseline: 1.1926x; 1.1926x over previous
#include <cuda_runtime.h>

typedef unsigned long long u64;

__device__ __forceinline__ u64 pk2(float lo, float hi){
  u64 r; asm("mov.b64 %0, {%1, %2};" : "=l"(r) : "f"(lo), "f"(hi)); return r;
}
__device__ __forceinline__ void upk2(u64 v, float& lo, float& hi){
  asm("mov.b64 {%0, %1}, %2;" : "=f"(lo), "=f"(hi) : "l"(v));
}
__device__ __forceinline__ u64 ffma2(u64 a, u64 b, u64 c){
  u64 r; asm("fma.rn.f32x2 %0, %1, %2, %3;" : "=l"(r) : "l"(a), "l"(b), "l"(c)); return r;
}
__device__ __forceinline__ u64 fmul2(u64 a, u64 b){
  u64 r; asm("mul.rn.f32x2 %0, %1, %2;" : "=l"(r) : "l"(a), "l"(b)); return r;
}
__device__ __forceinline__ u64 fadd2(u64 a, u64 b){
  u64 r; asm("add.rn.f32x2 %0, %1, %2;" : "=l"(r) : "l"(a), "l"(b)); return r;
}

#define NWARP 8
#define GRID_BLOCKS 456   // 152 SMs * 3 resident blocks (matched to residency)

// Fused PillarVFE, persistent warps, DEPTH-2 software pipeline:
// register sets A/B hold pillars p and p+NW; processing set S refills S with
// pillar p+2NW, so each LDG has ~1.5 iterations to complete (DRAM hidden).
//   pre[n,o] = A[o]x + B[o]y + C[o]z + D[o]w + bias_p[o]
//   out[o]   = max( max_{n<npts} pre, npts<32 ? bn_bias[o] : -inf, 0 )
__global__ __launch_bounds__(256, 3) void pillar_vfe_kernel(
    const float4* __restrict__ voxels,   // [P,32] xyzw
    const float*  __restrict__ W,        // [64,9]
    const float*  __restrict__ gamma,
    const float*  __restrict__ beta,
    const float*  __restrict__ rmean,
    const float*  __restrict__ rvar,
    const int*    __restrict__ vnum,     // [P]
    const int*    __restrict__ vcoords,  // [P,4] (b,z,y,x)
    float*        __restrict__ out,      // [P,64]
    int P)
{
  __shared__ float cf[10][64];                         // folded coefficients
  __shared__ __align__(16) float shp[NWARP][2][4][32]; // [warp][set][row][pt]

  int tid = threadIdx.x;
  if (tid < 64) {
    int o = tid;
    float s = gamma[o] / sqrtf(rvar[o] + 1e-3f);
    const float* w = W + o * 9;
    float w0=w[0], w1=w[1], w2=w[2], w3=w[3], w4=w[4], w5=w[5], w6=w[6], w7=w[7], w8=w[8];
    float S0 = w0 + w7, S1 = w1 + w8;   // xc / yc channels duplicated (c0+c7, c1+c8)
    cf[0][o] = s * (S0 + w4);           // * x
    cf[1][o] = s * (S1 + w5);           // * y
    cf[2][o] = s * (w2 + w6);           // * z
    cf[3][o] = s * w3;                  // * intensity
    cf[4][o] = s * S0;                  // * cx
    cf[5][o] = s * S1;                  // * cy
    cf[6][o] = s * w4;                  // * mx
    cf[7][o] = s * w5;                  // * my
    cf[8][o] = s * w6;                  // * mz
    cf[9][o] = beta[o] - rmean[o] * s;  // BN bias (= masked-point pre-activation)
  }
  __syncthreads();

  int lane = tid & 31;
  int wrp  = tid >> 5;
  int NWt  = gridDim.x * NWARP;
  int p    = blockIdx.x * NWARP + wrp;
  if (p >= P) return;

  // ---- Hoisted per-warp constants. Lane owns channels c0=2*lane, c1=2*lane+1.
  int c0 = 2 * lane, c1 = 2 * lane + 1;
  u64 pA0 = pk2(cf[0][c0], cf[0][c0]), pA1 = pk2(cf[0][c1], cf[0][c1]);
  u64 pB0 = pk2(cf[1][c0], cf[1][c0]), pB1 = pk2(cf[1][c1], cf[1][c1]);
  u64 pC0 = pk2(cf[2][c0], cf[2][c0]), pC1 = pk2(cf[2][c1], cf[2][c1]);
  u64 pD0 = pk2(cf[3][c0], cf[3][c0]), pD1 = pk2(cf[3][c1], cf[3][c1]);
  float n4a = -cf[4][c0], n4b = -cf[4][c1];
  float n5a = -cf[5][c0], n5b = -cf[5][c1];
  float n6a = -cf[6][c0], n6b = -cf[6][c1];
  float n7a = -cf[7][c0], n7b = -cf[7][c1];
  float n8a = -cf[8][c0], n8b = -cf[8][c1];
  float bb0 = cf[9][c0], bb1 = cf[9][c1];
  float rbb0 = fmaxf(bb0, 0.0f), rbb1 = fmaxf(bb1, 0.0f);

  float* sbA = &shp[wrp][0][0][0];
  float* sbB = &shp[wrp][1][0][0];

  // ---- Prologue: load pillar p into set A, pillar p+NW into set B.
  float4 vA = voxels[(size_t)p * 32 + lane];
  int   npA = vnum[p];
  int2 cyxA = *reinterpret_cast<const int2*>(vcoords + (size_t)p * 4 + 2);
  float4 vB; int npB = 1; int2 cyxB = make_int2(0, 0);
  {
    int pb = p + NWt;
    if (pb < P) {
      vB   = voxels[(size_t)pb * 32 + lane];
      npB  = vnum[pb];
      cyxB = *reinterpret_cast<const int2*>(vcoords + (size_t)pb * 4 + 2);
    }
  }

  // One half-iteration: processes pillar `p` held in (V,NP,CYX), refills the
  // same registers with pillar p+2*NW, stores result, then p += NW.
#define HALF(V, NP, CYX, SB)                                                  \
  {                                                                           \
    int  npc = NP;                                                            \
    int2 cc  = CYX;                                                           \
    /* Mean sums over ALL 32 raw points (reference sums unmasked). */         \
    u64  sxy = pk2(V.x, V.y);                                                 \
    float sz = V.z;                                                           \
    _Pragma("unroll")                                                         \
    for (int off = 16; off; off >>= 1) {                                      \
      u64 o2 = __shfl_xor_sync(0xffffffffu, sxy, off);                        \
      float oz = __shfl_xor_sync(0xffffffffu, sz, off);                       \
      sxy = fadd2(sxy, o2);                                                   \
      sz += oz;                                                               \
    }                                                                         \
    /* Stage transposed; pad invalid lanes with point 0 (max-idempotent). */  \
    float x0 = __shfl_sync(0xffffffffu, V.x, 0);                              \
    float y0 = __shfl_sync(0xffffffffu, V.y, 0);                              \
    float z0 = __shfl_sync(0xffffffffu, V.z, 0);                              \
    float w0 = __shfl_sync(0xffffffffu, V.w, 0);                              \
    bool valid = (lane < npc);                                                \
    SB[lane]      = valid ? V.x : x0;                                         \
    SB[32 + lane] = valid ? V.y : y0;                                         \
    SB[64 + lane] = valid ? V.z : z0;                                         \
    SB[96 + lane] = valid ? V.w : w0;                                         \
    /* Refill this set with pillar p+2NW (consumed ~1.5 iterations later). */ \
    {                                                                         \
      int pf = p + 2 * NWt;                                                   \
      if (pf < P) {                                                           \
        V   = voxels[(size_t)pf * 32 + lane];                                 \
        NP  = vnum[pf];                                                       \
        CYX = *reinterpret_cast<const int2*>(vcoords + (size_t)pf * 4 + 2);   \
      }                                                                       \
    }                                                                         \
    __syncwarp();                                                             \
    /* Quad loop: guarded, immediate LDS offsets. */                          \
    const ulonglong2* rq = reinterpret_cast<const ulonglong2*>(SB);           \
    float m0 = -3.4e38f, m1 = -3.4e38f;                                       \
    int trips = (npc + 3) >> 2;                                               \
    _Pragma("unroll")                                                         \
    for (int q = 0; q < 8; q++) {                                             \
      if (q >= trips) break;                                                  \
      ulonglong2 X = rq[q],      Y  = rq[8 + q];                              \
      ulonglong2 Z = rq[16 + q], Wv = rq[24 + q];                             \
      u64 s01 = fmul2(pA0, X.x);  s01 = ffma2(pB0, Y.x, s01);                 \
      u64 s23 = fmul2(pA0, X.y);  s23 = ffma2(pB0, Y.y, s23);                 \
      u64 r01 = fmul2(pA1, X.x);  r01 = ffma2(pB1, Y.x, r01);                 \
      u64 r23 = fmul2(pA1, X.y);  r23 = ffma2(pB1, Y.y, r23);                 \
      s01 = ffma2(pC0, Z.x, s01); s01 = ffma2(pD0, Wv.x, s01);                \
      s23 = ffma2(pC0, Z.y, s23); s23 = ffma2(pD0, Wv.y, s23);                \
      r01 = ffma2(pC1, Z.x, r01); r01 = ffma2(pD1, Wv.x, r01);                \
      r23 = ffma2(pC1, Z.y, r23); r23 = ffma2(pD1, Wv.y, r23);                \
      float a, b, c, d;                                                       \
      upk2(s01, a, b); upk2(s23, c, d);                                       \
      m0 = fmaxf(m0, fmaxf(fmaxf(a, b), fmaxf(c, d)));                        \
      upk2(r01, a, b); upk2(r23, c, d);                                       \
      m1 = fmaxf(m1, fmaxf(fmaxf(a, b), fmaxf(c, d)));                        \
    }                                                                         \
    /* Scalar bias chains + epilogue. */                                      \
    float rn = __fdividef(1.0f, (float)npc);                                  \
    float sx, sy;                                                             \
    upk2(sxy, sx, sy);                                                        \
    float mx = sx * rn, my = sy * rn, mz = sz * rn;                           \
    float cx = fmaf((float)cc.y, 0.16f, 0.08f);                               \
    float cy = fmaf((float)cc.x, 0.16f, -39.6f);                              \
    float bias0 = fmaf(mz, n8a, fmaf(my, n7a, fmaf(mx, n6a,                   \
                  fmaf(cy, n5a, fmaf(cx, n4a, bb0)))));                       \
    float bias1 = fmaf(mz, n8b, fmaf(my, n7b, fmaf(mx, n6b,                   \
                  fmaf(cy, n5b, fmaf(cx, n4b, bb1)))));                       \
    float g0 = (npc < 32) ? rbb0 : 0.0f;                                      \
    float g1 = (npc < 32) ? rbb1 : 0.0f;                                      \
    float2 res = make_float2(fmaxf(m0 + bias0, g0), fmaxf(m1 + bias1, g1));   \
    reinterpret_cast<float2*>(out)[(size_t)p * 32 + lane] = res;              \
    p += NWt;                                                                 \
  }

  for (;;) {
    HALF(vA, npA, cyxA, sbA)
    if (p >= P) break;
    HALF(vB, npB, cyxB, sbB)
    if (p >= P) break;
  }
#undef HALF
}

extern "C" void kernel_launch(void* const* d_in, const int* in_sizes, int n_in,
                              void* d_out, int out_size) {
  const float4* voxels = (const float4*)d_in[0];
  const float*  W      = (const float*)d_in[1];
  const float*  gamma  = (const float*)d_in[2];
  const float*  beta   = (const float*)d_in[3];
  const float*  rmean  = (const float*)d_in[4];
  const float*  rvar   = (const float*)d_in[5];
  const int*    vnum   = (const int*)d_in[6];
  const int*    vcrd   = (const int*)d_in[7];
  float* out = (float*)d_out;

  int P = in_sizes[6];
  int needed = (P + NWARP - 1) / NWARP;
  int blocks = needed < GRID_BLOCKS ? needed : GRID_BLOCKS;
  pillar_vfe_kernel<<<blocks, 256>>>(voxels, W, gamma, beta, rmean, rvar,
                                     vnum, vcrd, out, P);
}